// round 1
// baseline (speedup 1.0000x reference)
#include <cuda_runtime.h>
#include <math.h>

// Problem constants (fixed by reference)
#define B_ANCH 2048
#define P_POS  4
#define D_DIM  256
#define NNEG   32768
#define INV_T  20.0f
#define ALPHA_W 0.1f
#define EPS_N  1e-12f

// Tiling
#define BM 64
#define BN 64
#define NCHUNK 32
#define CHUNK (NNEG / NCHUNK)   // 1024 negatives per block
#define SUBT  (CHUNK / BN)      // 16 sub-tiles
#define SPAD  258               // padded row stride (floats), conflict-free LDS.64
#define SMEM_BYTES ((BM + BN) * SPAD * 4)

typedef unsigned long long ull;

// Scratch (allocation-free rule: __device__ globals)
__device__ float g_an[B_ANCH * D_DIM];     // normalized anchors
__device__ float g_nn[NNEG * D_DIM];       // normalized negatives
__device__ float g_pos[B_ANCH * P_POS];    // pos_sim (already * 1/T)
__device__ float g_ps[NCHUNK * B_ANCH];    // partial sum-exp per (chunk, anchor)

__device__ __forceinline__ ull ffma2(ull a, ull b, ull c) {
    ull d;
    asm("fma.rn.f32x2 %0, %1, %2, %3;" : "=l"(d) : "l"(a), "l"(b), "l"(c));
    return d;
}

__device__ __forceinline__ float logaddexpf_(float a, float b) {
    float hi = fmaxf(a, b);
    float lo = fminf(a, b);
    return hi + log1pf(expf(lo - hi));
}

// ---------------------------------------------------------------------------
// L2-normalize rows (warp per row of 256 floats). target: 0 -> g_an, 1 -> g_nn
// ---------------------------------------------------------------------------
__global__ void norm_rows_kernel(const float* __restrict__ in, int rows, int target) {
    int w = (blockIdx.x * blockDim.x + threadIdx.x) >> 5;
    int lane = threadIdx.x & 31;
    if (w >= rows) return;
    float* outbase = target ? g_nn : g_an;

    const float4* src = (const float4*)(in + (size_t)w * D_DIM);
    float4 v0 = src[lane];
    float4 v1 = src[lane + 32];
    float ss = v0.x * v0.x + v0.y * v0.y + v0.z * v0.z + v0.w * v0.w
             + v1.x * v1.x + v1.y * v1.y + v1.z * v1.z + v1.w * v1.w;
#pragma unroll
    for (int o = 16; o > 0; o >>= 1) ss += __shfl_xor_sync(0xffffffffu, ss, o);
    float inv = 1.0f / fmaxf(sqrtf(ss), EPS_N);

    float4* dst = (float4*)(outbase + (size_t)w * D_DIM);
    v0.x *= inv; v0.y *= inv; v0.z *= inv; v0.w *= inv;
    v1.x *= inv; v1.y *= inv; v1.z *= inv; v1.w *= inv;
    dst[lane] = v0;
    dst[lane + 32] = v1;
}

// ---------------------------------------------------------------------------
// pos_sim[b][j] = dot(a_n[b], normalize(p[b,j])) / T   (warp per pair)
// ---------------------------------------------------------------------------
__global__ void pos_sim_kernel(const float* __restrict__ pos) {
    int w = (blockIdx.x * blockDim.x + threadIdx.x) >> 5;  // pair index b*P+j
    int lane = threadIdx.x & 31;
    if (w >= B_ANCH * P_POS) return;
    int b = w >> 2;

    const float4* psrc = (const float4*)(pos + (size_t)w * D_DIM);
    const float4* asrc = (const float4*)(g_an + (size_t)b * D_DIM);
    float ss = 0.f, dot = 0.f;
#pragma unroll
    for (int t = 0; t < 2; ++t) {
        float4 pv = psrc[lane + 32 * t];
        float4 av = asrc[lane + 32 * t];
        ss  += pv.x * pv.x + pv.y * pv.y + pv.z * pv.z + pv.w * pv.w;
        dot += pv.x * av.x + pv.y * av.y + pv.z * av.z + pv.w * av.w;
    }
#pragma unroll
    for (int o = 16; o > 0; o >>= 1) {
        ss  += __shfl_xor_sync(0xffffffffu, ss, o);
        dot += __shfl_xor_sync(0xffffffffu, dot, o);
    }
    if (lane == 0)
        g_pos[w] = dot / fmaxf(sqrtf(ss), EPS_N) * INV_T;
}

// ---------------------------------------------------------------------------
// Main fused GEMM + partial sum-exp.
// grid (B/BM, NCHUNK), 256 threads (16x16), 4x4 micro-tile, f32x2-packed over k.
// Partial LSE uses fixed shift 20.0 (|sim| <= 20 since inputs are normalized).
// ---------------------------------------------------------------------------
__global__ void __launch_bounds__(256, 1) neg_partial_kernel() {
    extern __shared__ float smem[];
    float* a_s = smem;                 // [BM][SPAD]
    float* n_s = smem + BM * SPAD;     // [BN][SPAD]

    int tid = threadIdx.x;
    int tx = tid & 15;
    int ty = tid >> 4;
    int aBase = blockIdx.x * BM;
    int nBase = blockIdx.y * CHUNK;

    // Fill anchor tile (64 x 256)
    for (int i = tid; i < BM * 64; i += 256) {
        int r = i >> 6;
        int c = (i & 63) << 2;
        float4 v = *(const float4*)(g_an + (size_t)(aBase + r) * D_DIM + c);
        float* dstp = a_s + r * SPAD + c;
        *(float2*)(dstp)     = make_float2(v.x, v.y);
        *(float2*)(dstp + 2) = make_float2(v.z, v.w);
    }

    const float* ap[4];
    const float* np[4];
#pragma unroll
    for (int i = 0; i < 4; ++i) ap[i] = a_s + (ty + (i << 4)) * SPAD;
#pragma unroll
    for (int j = 0; j < 4; ++j) np[j] = n_s + (tx + (j << 4)) * SPAD;

    float sacc[4] = {0.f, 0.f, 0.f, 0.f};

#pragma unroll 1
    for (int sub = 0; sub < SUBT; ++sub) {
        const float* nptr = g_nn + (size_t)(nBase + (sub << 6)) * D_DIM;
        __syncthreads();   // previous k-loop done (and a_s fill on first iter)
#pragma unroll
        for (int u = 0; u < 16; ++u) {
            int i = tid + (u << 8);
            int r = i >> 6;
            int c = (i & 63) << 2;
            float4 v = *(const float4*)(nptr + r * D_DIM + c);
            float* dstp = n_s + r * SPAD + c;
            *(float2*)(dstp)     = make_float2(v.x, v.y);
            *(float2*)(dstp + 2) = make_float2(v.z, v.w);
        }
        __syncthreads();

        ull acc[4][4];
#pragma unroll
        for (int i = 0; i < 4; ++i)
#pragma unroll
            for (int j = 0; j < 4; ++j) acc[i][j] = 0ull;

#pragma unroll 8
        for (int kp = 0; kp < 128; ++kp) {
            ull av[4], nv[4];
#pragma unroll
            for (int i = 0; i < 4; ++i) av[i] = *(const ull*)(ap[i] + (kp << 1));
#pragma unroll
            for (int j = 0; j < 4; ++j) nv[j] = *(const ull*)(np[j] + (kp << 1));
#pragma unroll
            for (int i = 0; i < 4; ++i)
#pragma unroll
                for (int j = 0; j < 4; ++j)
                    acc[i][j] = ffma2(av[i], nv[j], acc[i][j]);
        }

#pragma unroll
        for (int i = 0; i < 4; ++i) {
            float t = 0.f;
#pragma unroll
            for (int j = 0; j < 4; ++j) {
                float lo = __uint_as_float((unsigned)(acc[i][j]));
                float hi = __uint_as_float((unsigned)(acc[i][j] >> 32));
                float sim = (lo + hi) * INV_T;
                t += __expf(sim - 20.0f);
            }
            sacc[i] += t;
        }
    }

    // Reduce across the 16 tx lanes (xor<16 stays inside the half-warp group)
#pragma unroll
    for (int i = 0; i < 4; ++i) {
        float v = sacc[i];
        v += __shfl_xor_sync(0xffffffffu, v, 1);
        v += __shfl_xor_sync(0xffffffffu, v, 2);
        v += __shfl_xor_sync(0xffffffffu, v, 4);
        v += __shfl_xor_sync(0xffffffffu, v, 8);
        sacc[i] = v;
    }
    if (tx == 0) {
#pragma unroll
        for (int i = 0; i < 4; ++i)
            g_ps[blockIdx.y * B_ANCH + aBase + ty + (i << 4)] = sacc[i];
    }
}

// ---------------------------------------------------------------------------
// Finalize: combine partials -> neg_lse; pair + weighted terms; tree-reduce.
// Single block => deterministic.
// ---------------------------------------------------------------------------
__global__ void finalize_kernel(const int* __restrict__ counts, float* __restrict__ out) {
    __shared__ float red[256];
    int tid = threadIdx.x;
    float local = 0.f;

    for (int b = tid; b < B_ANCH; b += 256) {
        float ssum = 0.f;
#pragma unroll
        for (int c = 0; c < NCHUNK; ++c) ssum += g_ps[c * B_ANCH + b];
        float lse = 20.0f + logf(ssum);

        int cnt = counts[b];
        float pv[P_POS];
        float m4 = -INFINITY;
#pragma unroll
        for (int j = 0; j < P_POS; ++j) {
            pv[j] = g_pos[b * P_POS + j];
            m4 = fmaxf(m4, pv[j]);
        }
        float se = 0.f, wp = 0.f, al = 0.f;
#pragma unroll
        for (int j = 0; j < P_POS; ++j) {
            if (j < cnt) al += logaddexpf_(pv[j], lse) - pv[j];
            float e = expf(pv[j] - m4);
            se += e;
            wp += e * pv[j];
        }
        if (cnt > 1) {
            float wps = wp / se;
            al += ALPHA_W * (logaddexpf_(wps, lse) - wps);
        }
        local += al;
    }

    red[tid] = local;
    __syncthreads();
    for (int o = 128; o > 0; o >>= 1) {
        if (tid < o) red[tid] += red[tid + o];
        __syncthreads();
    }
    if (tid == 0) out[0] = red[0] / (float)B_ANCH;
}

// ---------------------------------------------------------------------------
extern "C" void kernel_launch(void* const* d_in, const int* in_sizes, int n_in,
                              void* d_out, int out_size) {
    const float* anc = (const float*)d_in[0];
    const float* pos = (const float*)d_in[1];
    const float* neg = (const float*)d_in[2];
    const int*   cnt = (const int*)d_in[3];
    float* out = (float*)d_out;

    (void)in_sizes; (void)n_in; (void)out_size;

    cudaFuncSetAttribute(neg_partial_kernel,
                         cudaFuncAttributeMaxDynamicSharedMemorySize, SMEM_BYTES);

    norm_rows_kernel<<<B_ANCH / 8, 256>>>(anc, B_ANCH, 0);
    norm_rows_kernel<<<NNEG / 8, 256>>>(neg, NNEG, 1);
    pos_sim_kernel<<<(B_ANCH * P_POS) / 8, 256>>>(pos);
    neg_partial_kernel<<<dim3(B_ANCH / BM, NCHUNK), 256, SMEM_BYTES>>>();
    finalize_kernel<<<1, 256>>>(cnt, out);
}

// round 4
// speedup vs baseline: 11.7879x; 11.7879x over previous
#include <cuda_runtime.h>
#include <cuda_bf16.h>
#include <stdint.h>
#include <math.h>

// Problem constants
#define B_ANCH 2048
#define P_POS  4
#define D_DIM  256
#define NNEG   32768
#define INV_T  20.0f
#define ALPHA_W 0.1f
#define EPS_N  1e-12f
#define LOG2E20 28.853900817779268f   // 20 * log2(e)

// Tiling
#define MT     128               // anchors per CTA
#define NT     128               // negatives per subtile
#define NSPLIT 32
#define CHUNK  (NNEG / NSPLIT)   // 1024
#define SUBT   (CHUNK / NT)      // 8
#define TILE_BYTES (MT * D_DIM * 2)      // 64 KB
#define SMEM_TOTAL (3 * TILE_BYTES)      // A + B0 + B1 = 192 KB

// ---------------- scratch (allocation-free rule) ----------------
__device__ __align__(16) float          g_an[B_ANCH * D_DIM];
__device__ __align__(16) __nv_bfloat16  g_an_bf[B_ANCH * D_DIM];
__device__ __align__(16) __nv_bfloat16  g_nn_bf[NNEG * D_DIM];
__device__ float g_pos[B_ANCH * P_POS];
__device__ float g_ps[NSPLIT * B_ANCH];

// ---------------- helpers ----------------
__device__ __forceinline__ uint32_t smem_u32(const void* p) {
    uint32_t a;
    asm("{ .reg .u64 t; cvta.to.shared.u64 t, %1; cvt.u32.u64 %0, t; }" : "=r"(a) : "l"(p));
    return a;
}
__device__ __forceinline__ void ldsm_x4(uint32_t* r, uint32_t addr) {
    asm volatile("ldmatrix.sync.aligned.m8n8.x4.shared.b16 {%0,%1,%2,%3}, [%4];"
                 : "=r"(r[0]), "=r"(r[1]), "=r"(r[2]), "=r"(r[3]) : "r"(addr));
}
__device__ __forceinline__ void mma_bf16(float* d, const uint32_t* a, const uint32_t* b) {
    asm volatile("mma.sync.aligned.m16n8k16.row.col.f32.bf16.bf16.f32 "
                 "{%0,%1,%2,%3}, {%4,%5,%6,%7}, {%8,%9}, {%0,%1,%2,%3};"
                 : "+f"(d[0]), "+f"(d[1]), "+f"(d[2]), "+f"(d[3])
                 : "r"(a[0]), "r"(a[1]), "r"(a[2]), "r"(a[3]), "r"(b[0]), "r"(b[1]));
}
__device__ __forceinline__ float ex2f(float x) {
    float y;
    asm("ex2.approx.ftz.f32 %0, %1;" : "=f"(y) : "f"(x));
    return y;
}
__device__ __forceinline__ float logaddexpf_(float a, float b) {
    float hi = fmaxf(a, b), lo = fminf(a, b);
    return hi + log1pf(expf(lo - hi));
}

// 128 rows x 256 bf16 (512B rows), 16B chunks XOR-swizzled: chunk' = chunk ^ (row&7)
__device__ __forceinline__ void cp_fill(uint32_t dstBase, const __nv_bfloat16* src, int tid) {
#pragma unroll
    for (int i = 0; i < 16; ++i) {
        int idx = tid + (i << 8);
        int r = idx >> 5;
        int c = idx & 31;
        uint32_t dst = dstBase + r * 512 + (uint32_t)((c ^ (r & 7)) << 4);
        const void* g = (const void*)(src + (size_t)r * D_DIM + c * 8);
        asm volatile("cp.async.cg.shared.global [%0], [%1], 16;" :: "r"(dst), "l"(g) : "memory");
    }
}

// ---------------------------------------------------------------------------
// Normalize rows (warp per row). mode 0 -> anchors (fp32+bf16), 1 -> negatives (bf16)
// ---------------------------------------------------------------------------
__global__ void norm_rows_kernel(const float* __restrict__ in, int rows, int mode) {
    int w = (blockIdx.x * blockDim.x + threadIdx.x) >> 5;
    int lane = threadIdx.x & 31;
    if (w >= rows) return;

    const float4* src = (const float4*)(in + (size_t)w * D_DIM);
    float4 v0 = src[lane];
    float4 v1 = src[lane + 32];
    float ss = v0.x * v0.x + v0.y * v0.y + v0.z * v0.z + v0.w * v0.w
             + v1.x * v1.x + v1.y * v1.y + v1.z * v1.z + v1.w * v1.w;
#pragma unroll
    for (int o = 16; o > 0; o >>= 1) ss += __shfl_xor_sync(0xffffffffu, ss, o);
    float inv = 1.0f / fmaxf(sqrtf(ss), EPS_N);
    v0.x *= inv; v0.y *= inv; v0.z *= inv; v0.w *= inv;
    v1.x *= inv; v1.y *= inv; v1.z *= inv; v1.w *= inv;

    __nv_bfloat162* b2 = (__nv_bfloat162*)((mode ? g_nn_bf : g_an_bf) + (size_t)w * D_DIM);
    b2[lane * 2]            = __nv_bfloat162(__float2bfloat16_rn(v0.x), __float2bfloat16_rn(v0.y));
    b2[lane * 2 + 1]        = __nv_bfloat162(__float2bfloat16_rn(v0.z), __float2bfloat16_rn(v0.w));
    b2[(lane + 32) * 2]     = __nv_bfloat162(__float2bfloat16_rn(v1.x), __float2bfloat16_rn(v1.y));
    b2[(lane + 32) * 2 + 1] = __nv_bfloat162(__float2bfloat16_rn(v1.z), __float2bfloat16_rn(v1.w));

    if (mode == 0) {
        float4* dst = (float4*)(g_an + (size_t)w * D_DIM);
        dst[lane] = v0;
        dst[lane + 32] = v1;
    }
}

// ---------------------------------------------------------------------------
// pos_sim (fp32, warp per pair)
// ---------------------------------------------------------------------------
__global__ void pos_sim_kernel(const float* __restrict__ pos) {
    int w = (blockIdx.x * blockDim.x + threadIdx.x) >> 5;
    int lane = threadIdx.x & 31;
    if (w >= B_ANCH * P_POS) return;
    int b = w >> 2;

    const float4* psrc = (const float4*)(pos + (size_t)w * D_DIM);
    const float4* asrc = (const float4*)(g_an + (size_t)b * D_DIM);
    float ss = 0.f, dot = 0.f;
#pragma unroll
    for (int t = 0; t < 2; ++t) {
        float4 pv = psrc[lane + 32 * t];
        float4 av = asrc[lane + 32 * t];
        ss  += pv.x * pv.x + pv.y * pv.y + pv.z * pv.z + pv.w * pv.w;
        dot += pv.x * av.x + pv.y * av.y + pv.z * av.z + pv.w * av.w;
    }
#pragma unroll
    for (int o = 16; o > 0; o >>= 1) {
        ss  += __shfl_xor_sync(0xffffffffu, ss, o);
        dot += __shfl_xor_sync(0xffffffffu, dot, o);
    }
    if (lane == 0)
        g_pos[w] = dot / fmaxf(sqrtf(ss), EPS_N) * INV_T;
}

// ---------------------------------------------------------------------------
// Main: warp-MMA GEMM + fused exp partial-sum. grid (16, NSPLIT), 256 thr (8 warps)
// ---------------------------------------------------------------------------
__global__ void __launch_bounds__(256, 1) neg_mma_kernel() {
    extern __shared__ char smem[];
    __shared__ float wsum[4][MT];

    const uint32_t Abase = smem_u32(smem);
    const uint32_t Bb[2] = { Abase + TILE_BYTES, Abase + 2 * TILE_BYTES };

    int tid = threadIdx.x;
    int l = tid & 31;
    int wid = tid >> 5;
    int warp_m = wid >> 2;      // 0..1
    int warp_n = wid & 3;       // 0..3
    int aBase = blockIdx.x * MT;
    int nBase = blockIdx.y * CHUNK;

    const __nv_bfloat16* Ag = g_an_bf + (size_t)aBase * D_DIM;
    const __nv_bfloat16* Bg = g_nn_bf + (size_t)nBase * D_DIM;

    cp_fill(Abase, Ag, tid);
    cp_fill(Bb[0], Bg, tid);
    asm volatile("cp.async.commit_group;" ::: "memory");
    asm volatile("cp.async.wait_group 0;" ::: "memory");
    __syncthreads();

    // ldmatrix lane address bases.
    // A x4 (per m-frag): row = warp_m*64 + mi*16 + (l&15), chunk = 2*ks + (l>>4)
    uint32_t a_base[4], a_s[4];
    {
        int arow_l = l & 15;
#pragma unroll
        for (int mi = 0; mi < 4; ++mi) {
            int row = warp_m * 64 + mi * 16 + arow_l;
            a_base[mi] = Abase + row * 512;
            a_s[mi] = (uint32_t)((row & 7) << 4);
        }
    }
    const uint32_t ac0 = (uint32_t)(l >> 4);           // 0/1
    // B x4 (per n-frag pair j): row = warp_n*32 + j*16 + (l&7) + ((l>>4)<<3),
    //                           chunk = 2*ks + ((l>>3)&1)
    uint32_t b_off[2], b_s[2];
    {
        int brow_l = (l & 7) + ((l >> 4) << 3);
#pragma unroll
        for (int j = 0; j < 2; ++j) {
            int row = warp_n * 32 + j * 16 + brow_l;
            b_off[j] = (uint32_t)(row * 512);
            b_s[j] = (uint32_t)((row & 7) << 4);
        }
    }
    const uint32_t bc0 = (uint32_t)((l >> 3) & 1);

    float rowsum[8];
#pragma unroll
    for (int i = 0; i < 8; ++i) rowsum[i] = 0.f;

#pragma unroll 1
    for (int sub = 0; sub < SUBT; ++sub) {
        uint32_t cur = Bb[sub & 1];
        if (sub + 1 < SUBT)
            cp_fill(Bb[(sub + 1) & 1], Bg + (size_t)(sub + 1) * NT * D_DIM, tid);
        asm volatile("cp.async.commit_group;" ::: "memory");

        float acc[4][4][4];
#pragma unroll
        for (int mi = 0; mi < 4; ++mi)
#pragma unroll
            for (int nj = 0; nj < 4; ++nj)
#pragma unroll
                for (int q = 0; q < 4; ++q) acc[mi][nj][q] = 0.f;

#pragma unroll
        for (int ks = 0; ks < 16; ++ks) {
            uint32_t af[4][4];
#pragma unroll
            for (int mi = 0; mi < 4; ++mi)
                ldsm_x4(af[mi], a_base[mi] + ((((uint32_t)(ks * 2) + ac0) << 4) ^ a_s[mi]));
            uint32_t bf[2][4];
#pragma unroll
            for (int j = 0; j < 2; ++j)
                ldsm_x4(bf[j], cur + b_off[j] + ((((uint32_t)(ks * 2) + bc0) << 4) ^ b_s[j]));
#pragma unroll
            for (int mi = 0; mi < 4; ++mi) {
                mma_bf16(acc[mi][0], af[mi], &bf[0][0]);
                mma_bf16(acc[mi][1], af[mi], &bf[0][2]);
                mma_bf16(acc[mi][2], af[mi], &bf[1][0]);
                mma_bf16(acc[mi][3], af[mi], &bf[1][2]);
            }
        }

        // exp epilogue: acc rows: c0,c1 -> row mi*16 + l/4 ; c2,c3 -> +8
#pragma unroll
        for (int mi = 0; mi < 4; ++mi) {
            float t0 = 0.f, t1 = 0.f;
#pragma unroll
            for (int nj = 0; nj < 4; ++nj) {
                t0 += ex2f(fmaf(acc[mi][nj][0], LOG2E20, -LOG2E20));
                t0 += ex2f(fmaf(acc[mi][nj][1], LOG2E20, -LOG2E20));
                t1 += ex2f(fmaf(acc[mi][nj][2], LOG2E20, -LOG2E20));
                t1 += ex2f(fmaf(acc[mi][nj][3], LOG2E20, -LOG2E20));
            }
            rowsum[mi * 2]     += t0;
            rowsum[mi * 2 + 1] += t1;
        }

        asm volatile("cp.async.wait_group 0;" ::: "memory");
        __syncthreads();
    }

    // Reduce across the 4 lanes (l%4) sharing each row; deterministic smem combine.
#pragma unroll
    for (int i = 0; i < 8; ++i) {
        float v = rowsum[i];
        v += __shfl_xor_sync(0xffffffffu, v, 1);
        v += __shfl_xor_sync(0xffffffffu, v, 2);
        rowsum[i] = v;
    }
    if ((l & 3) == 0) {
#pragma unroll
        for (int i = 0; i < 8; ++i) {
            int row = warp_m * 64 + (i >> 1) * 16 + (l >> 2) + (i & 1) * 8;
            wsum[warp_n][row] = rowsum[i];
        }
    }
    __syncthreads();
    if (tid < MT) {
        float v = wsum[0][tid] + wsum[1][tid] + wsum[2][tid] + wsum[3][tid];
        g_ps[blockIdx.y * B_ANCH + aBase + tid] = v;
    }
}

// ---------------------------------------------------------------------------
// Finalize (single block, deterministic)
// ---------------------------------------------------------------------------
__global__ void finalize_kernel(const int* __restrict__ counts, float* __restrict__ out) {
    __shared__ float red[256];
    int tid = threadIdx.x;
    float local = 0.f;

    for (int b = tid; b < B_ANCH; b += 256) {
        float ssum = 0.f;
#pragma unroll
        for (int c = 0; c < NSPLIT; ++c) ssum += g_ps[c * B_ANCH + b];
        float lse = 20.0f + logf(ssum);

        int cnt = counts[b];
        float pv[P_POS];
        float m4 = -INFINITY;
#pragma unroll
        for (int j = 0; j < P_POS; ++j) {
            pv[j] = g_pos[b * P_POS + j];
            m4 = fmaxf(m4, pv[j]);
        }
        float se = 0.f, wp = 0.f, al = 0.f;
#pragma unroll
        for (int j = 0; j < P_POS; ++j) {
            if (j < cnt) al += logaddexpf_(pv[j], lse) - pv[j];
            float e = expf(pv[j] - m4);
            se += e;
            wp += e * pv[j];
        }
        if (cnt > 1) {
            float wps = wp / se;
            al += ALPHA_W * (logaddexpf_(wps, lse) - wps);
        }
        local += al;
    }

    red[tid] = local;
    __syncthreads();
    for (int o = 128; o > 0; o >>= 1) {
        if (tid < o) red[tid] += red[tid + o];
        __syncthreads();
    }
    if (tid == 0) out[0] = red[0] / (float)B_ANCH;
}

// ---------------------------------------------------------------------------
extern "C" void kernel_launch(void* const* d_in, const int* in_sizes, int n_in,
                              void* d_out, int out_size) {
    const float* anc = (const float*)d_in[0];
    const float* pos = (const float*)d_in[1];
    const float* neg = (const float*)d_in[2];
    const int*   cnt = (const int*)d_in[3];
    float* out = (float*)d_out;
    (void)in_sizes; (void)n_in; (void)out_size;

    cudaFuncSetAttribute(neg_mma_kernel,
                         cudaFuncAttributeMaxDynamicSharedMemorySize, SMEM_TOTAL);

    norm_rows_kernel<<<B_ANCH / 8, 256>>>(anc, B_ANCH, 0);
    norm_rows_kernel<<<NNEG / 8, 256>>>(neg, NNEG, 1);
    pos_sim_kernel<<<(B_ANCH * P_POS) / 8, 256>>>(pos);
    neg_mma_kernel<<<dim3(B_ANCH / MT, NSPLIT), 256, SMEM_TOTAL>>>();
    finalize_kernel<<<1, 256>>>(cnt, out);
}

// round 6
// speedup vs baseline: 11.8158x; 1.0024x over previous
#include <cuda_runtime.h>
#include <cuda_bf16.h>
#include <stdint.h>
#include <math.h>

// Problem constants
#define B_ANCH 2048
#define P_POS  4
#define D_DIM  256
#define INV_T  20.0f
#define ALPHA_W 0.1f
#define EPS_N  1e-12f
#define LOG2E20 28.853900817779268f   // 20 * log2(e)

#define NNEG   32768
// Tiling
#define MT     128               // anchors per CTA
#define NT     128               // negatives per subtile
#define NSPLIT 64
#define CHUNK  (NNEG / NSPLIT)   // 512
#define SUBT   (CHUNK / NT)      // 4
#define TILE_BYTES (MT * D_DIM * 2)      // 64 KB
#define SMEM_TOTAL (3 * TILE_BYTES)      // A + B0 + B1 = 192 KB

// ---------------- scratch (allocation-free rule) ----------------
__device__ __align__(16) float          g_an[B_ANCH * D_DIM];
__device__ __align__(16) __nv_bfloat16  g_an_bf[B_ANCH * D_DIM];
__device__ __align__(16) __nv_bfloat16  g_nn_bf[NNEG * D_DIM];
__device__ float g_pos[B_ANCH * P_POS];
__device__ float g_ps[NSPLIT * B_ANCH];

// ---------------- helpers ----------------
__device__ __forceinline__ uint32_t smem_u32(const void* p) {
    uint32_t a;
    asm("{ .reg .u64 t; cvta.to.shared.u64 t, %1; cvt.u32.u64 %0, t; }" : "=r"(a) : "l"(p));
    return a;
}
__device__ __forceinline__ void ldsm_x4(uint32_t* r, uint32_t addr) {
    asm volatile("ldmatrix.sync.aligned.m8n8.x4.shared.b16 {%0,%1,%2,%3}, [%4];"
                 : "=r"(r[0]), "=r"(r[1]), "=r"(r[2]), "=r"(r[3]) : "r"(addr));
}
__device__ __forceinline__ void mma_bf16(float* d, const uint32_t* a, const uint32_t* b) {
    asm volatile("mma.sync.aligned.m16n8k16.row.col.f32.bf16.bf16.f32 "
                 "{%0,%1,%2,%3}, {%4,%5,%6,%7}, {%8,%9}, {%0,%1,%2,%3};"
                 : "+f"(d[0]), "+f"(d[1]), "+f"(d[2]), "+f"(d[3])
                 : "r"(a[0]), "r"(a[1]), "r"(a[2]), "r"(a[3]), "r"(b[0]), "r"(b[1]));
}
__device__ __forceinline__ float ex2f(float x) {
    float y;
    asm("ex2.approx.ftz.f32 %0, %1;" : "=f"(y) : "f"(x));
    return y;
}
__device__ __forceinline__ float logaddexpf_(float a, float b) {
    float hi = fmaxf(a, b), lo = fminf(a, b);
    return hi + log1pf(expf(lo - hi));
}

// 128 rows x 256 bf16 (512B rows), 16B chunks XOR-swizzled: chunk' = chunk ^ (row&7)
__device__ __forceinline__ void cp_fill(uint32_t dstBase, const __nv_bfloat16* src, int tid) {
#pragma unroll
    for (int i = 0; i < 16; ++i) {
        int idx = tid + (i << 8);
        int r = idx >> 5;
        int c = idx & 31;
        uint32_t dst = dstBase + r * 512 + (uint32_t)((c ^ (r & 7)) << 4);
        const void* g = (const void*)(src + (size_t)r * D_DIM + c * 8);
        asm volatile("cp.async.cg.shared.global [%0], [%1], 16;" :: "r"(dst), "l"(g) : "memory");
    }
}

// ---------------------------------------------------------------------------
// One M-half GEMM (2 mi x 4 nj frags) over current B subtile.
// If DRAIN, interleave ex2-drain of `pend` (the previous half, half index PH)
// at 2 values per k-step, accumulating into rowsum.
// ---------------------------------------------------------------------------
template<int HALF, int PH, bool DRAIN>
__device__ __forceinline__ void gemm_half(
    uint32_t Bcur,
    const uint32_t (&a_base)[4], const uint32_t (&a_s)[4],
    const uint32_t (&b_off)[2], const uint32_t (&b_s)[2],
    uint32_t ac0, uint32_t bc0,
    float (&acc)[32], float (&pend)[32], float (&rowsum)[8])
{
#pragma unroll
    for (int i = 0; i < 32; ++i) acc[i] = 0.f;
#pragma unroll
    for (int ks = 0; ks < 16; ++ks) {
        uint32_t af[2][4];
#pragma unroll
        for (int mi = 0; mi < 2; ++mi) {
            const int gm = HALF * 2 + mi;
            ldsm_x4(af[mi], a_base[gm] + ((((uint32_t)(ks * 2) + ac0) << 4) ^ a_s[gm]));
        }
        uint32_t bf[2][4];
#pragma unroll
        for (int j = 0; j < 2; ++j)
            ldsm_x4(bf[j], Bcur + b_off[j] + ((((uint32_t)(ks * 2) + bc0) << 4) ^ b_s[j]));
#pragma unroll
        for (int mi = 0; mi < 2; ++mi) {
            mma_bf16(&acc[(mi * 4 + 0) * 4], af[mi], &bf[0][0]);
            mma_bf16(&acc[(mi * 4 + 1) * 4], af[mi], &bf[0][2]);
            mma_bf16(&acc[(mi * 4 + 2) * 4], af[mi], &bf[1][0]);
            mma_bf16(&acc[(mi * 4 + 3) * 4], af[mi], &bf[1][2]);
        }
        if (DRAIN) {
#pragma unroll
            for (int t = 0; t < 2; ++t) {
                const int fi = ks * 2 + t;
                const int mi = fi >> 4;
                const int q  = fi & 3;
                rowsum[((PH * 2 + mi) << 1) + (q >> 1)] +=
                    ex2f(fmaf(pend[fi], LOG2E20, -LOG2E20));
            }
        }
    }
}

// ---------------------------------------------------------------------------
// Normalize rows (warp per row). mode 0 -> anchors (fp32+bf16), 1 -> negatives
// ---------------------------------------------------------------------------
__global__ void norm_rows_kernel(const float* __restrict__ in, int rows, int mode) {
    int w = (blockIdx.x * blockDim.x + threadIdx.x) >> 5;
    int lane = threadIdx.x & 31;
    if (w >= rows) return;

    const float4* src = (const float4*)(in + (size_t)w * D_DIM);
    float4 v0 = src[lane];
    float4 v1 = src[lane + 32];
    float ss = v0.x * v0.x + v0.y * v0.y + v0.z * v0.z + v0.w * v0.w
             + v1.x * v1.x + v1.y * v1.y + v1.z * v1.z + v1.w * v1.w;
#pragma unroll
    for (int o = 16; o > 0; o >>= 1) ss += __shfl_xor_sync(0xffffffffu, ss, o);
    float inv = 1.0f / fmaxf(sqrtf(ss), EPS_N);
    v0.x *= inv; v0.y *= inv; v0.z *= inv; v0.w *= inv;
    v1.x *= inv; v1.y *= inv; v1.z *= inv; v1.w *= inv;

    __nv_bfloat162* b2 = (__nv_bfloat162*)((mode ? g_nn_bf : g_an_bf) + (size_t)w * D_DIM);
    b2[lane * 2]            = __nv_bfloat162(__float2bfloat16_rn(v0.x), __float2bfloat16_rn(v0.y));
    b2[lane * 2 + 1]        = __nv_bfloat162(__float2bfloat16_rn(v0.z), __float2bfloat16_rn(v0.w));
    b2[(lane + 32) * 2]     = __nv_bfloat162(__float2bfloat16_rn(v1.x), __float2bfloat16_rn(v1.y));
    b2[(lane + 32) * 2 + 1] = __nv_bfloat162(__float2bfloat16_rn(v1.z), __float2bfloat16_rn(v1.w));

    if (mode == 0) {
        float4* dst = (float4*)(g_an + (size_t)w * D_DIM);
        dst[lane] = v0;
        dst[lane + 32] = v1;
    }
}

// ---------------------------------------------------------------------------
// pos_sim (fp32, warp per pair)
// ---------------------------------------------------------------------------
__global__ void pos_sim_kernel(const float* __restrict__ pos) {
    int w = (blockIdx.x * blockDim.x + threadIdx.x) >> 5;
    int lane = threadIdx.x & 31;
    if (w >= B_ANCH * P_POS) return;
    int b = w >> 2;

    const float4* psrc = (const float4*)(pos + (size_t)w * D_DIM);
    const float4* asrc = (const float4*)(g_an + (size_t)b * D_DIM);
    float ss = 0.f, dot = 0.f;
#pragma unroll
    for (int t = 0; t < 2; ++t) {
        float4 pv = psrc[lane + 32 * t];
        float4 av = asrc[lane + 32 * t];
        ss  += pv.x * pv.x + pv.y * pv.y + pv.z * pv.z + pv.w * pv.w;
        dot += pv.x * av.x + pv.y * av.y + pv.z * av.z + pv.w * av.w;
    }
#pragma unroll
    for (int o = 16; o > 0; o >>= 1) {
        ss  += __shfl_xor_sync(0xffffffffu, ss, o);
        dot += __shfl_xor_sync(0xffffffffu, dot, o);
    }
    if (lane == 0)
        g_pos[w] = dot / fmaxf(sqrtf(ss), EPS_N) * INV_T;
}

// ---------------------------------------------------------------------------
// Main: warp-MMA GEMM + pipelined exp partial-sum. grid (16, NSPLIT), 8 warps.
// ---------------------------------------------------------------------------
__global__ void __launch_bounds__(256, 1) neg_mma_kernel() {
    extern __shared__ char smem[];
    __shared__ float wsum[4][MT];

    const uint32_t Abase = smem_u32(smem);
    const uint32_t Bb[2] = { Abase + TILE_BYTES, Abase + 2 * TILE_BYTES };

    int tid = threadIdx.x;
    int l = tid & 31;
    int wid = tid >> 5;
    int warp_m = wid >> 2;      // 0..1
    int warp_n = wid & 3;       // 0..3
    int aBase = blockIdx.x * MT;
    int nBase = blockIdx.y * CHUNK;

    const __nv_bfloat16* Ag = g_an_bf + (size_t)aBase * D_DIM;
    const __nv_bfloat16* Bg = g_nn_bf + (size_t)nBase * D_DIM;

    cp_fill(Abase, Ag, tid);
    cp_fill(Bb[0], Bg, tid);
    asm volatile("cp.async.commit_group;" ::: "memory");
    asm volatile("cp.async.wait_group 0;" ::: "memory");
    __syncthreads();

    // ldmatrix lane address bases
    uint32_t a_base[4], a_s[4];
    {
        int arow_l = l & 15;
#pragma unroll
        for (int mi = 0; mi < 4; ++mi) {
            int row = warp_m * 64 + mi * 16 + arow_l;
            a_base[mi] = Abase + row * 512;
            a_s[mi] = (uint32_t)((row & 7) << 4);
        }
    }
    const uint32_t ac0 = (uint32_t)(l >> 4);
    uint32_t b_off[2], b_s[2];
    {
        int brow_l = (l & 7) + ((l >> 4) << 3);
#pragma unroll
        for (int j = 0; j < 2; ++j) {
            int row = warp_n * 32 + j * 16 + brow_l;
            b_off[j] = (uint32_t)(row * 512);
            b_s[j] = (uint32_t)((row & 7) << 4);
        }
    }
    const uint32_t bc0 = (uint32_t)((l >> 3) & 1);

    float rowsum[8];
#pragma unroll
    for (int i = 0; i < 8; ++i) rowsum[i] = 0.f;

    float accE[32], accO[32];

    // ---- subtile 0 (peeled: half0 has nothing to drain) ----
    if (SUBT > 1) cp_fill(Bb[1], Bg + (size_t)NT * D_DIM, tid);
    asm volatile("cp.async.commit_group;" ::: "memory");

    gemm_half<0, 1, false>(Bb[0], a_base, a_s, b_off, b_s, ac0, bc0, accE, accO, rowsum);
    gemm_half<1, 0, true >(Bb[0], a_base, a_s, b_off, b_s, ac0, bc0, accO, accE, rowsum);

    asm volatile("cp.async.wait_group 0;" ::: "memory");
    __syncthreads();

    // ---- steady state ----
#pragma unroll 1
    for (int sub = 1; sub < SUBT; ++sub) {
        uint32_t cur = Bb[sub & 1];
        if (sub + 1 < SUBT)
            cp_fill(Bb[(sub + 1) & 1], Bg + (size_t)(sub + 1) * NT * D_DIM, tid);
        asm volatile("cp.async.commit_group;" ::: "memory");

        gemm_half<0, 1, true>(cur, a_base, a_s, b_off, b_s, ac0, bc0, accE, accO, rowsum);
        gemm_half<1, 0, true>(cur, a_base, a_s, b_off, b_s, ac0, bc0, accO, accE, rowsum);

        asm volatile("cp.async.wait_group 0;" ::: "memory");
        __syncthreads();
    }

    // ---- final drain of accO (half 1) ----
#pragma unroll
    for (int fi = 0; fi < 32; ++fi) {
        const int mi = fi >> 4;
        const int q  = fi & 3;
        rowsum[((2 + mi) << 1) + (q >> 1)] += ex2f(fmaf(accO[fi], LOG2E20, -LOG2E20));
    }

    // Reduce across the 4 lanes (l%4) sharing each row; deterministic smem combine.
#pragma unroll
    for (int i = 0; i < 8; ++i) {
        float v = rowsum[i];
        v += __shfl_xor_sync(0xffffffffu, v, 1);
        v += __shfl_xor_sync(0xffffffffu, v, 2);
        rowsum[i] = v;
    }
    if ((l & 3) == 0) {
#pragma unroll
        for (int i = 0; i < 8; ++i) {
            int row = warp_m * 64 + (i >> 1) * 16 + (l >> 2) + (i & 1) * 8;
            wsum[warp_n][row] = rowsum[i];
        }
    }
    __syncthreads();
    if (tid < MT) {
        float v = wsum[0][tid] + wsum[1][tid] + wsum[2][tid] + wsum[3][tid];
        g_ps[blockIdx.y * B_ANCH + aBase + tid] = v;
    }
}

// ---------------------------------------------------------------------------
// Finalize (single block, deterministic)
// ---------------------------------------------------------------------------
__global__ void finalize_kernel(const int* __restrict__ counts, float* __restrict__ out) {
    __shared__ float red[256];
    int tid = threadIdx.x;
    float local = 0.f;

    for (int b = tid; b < B_ANCH; b += 256) {
        float ssum = 0.f;
#pragma unroll
        for (int c = 0; c < NSPLIT; ++c) ssum += g_ps[c * B_ANCH + b];
        float lse = 20.0f + logf(ssum);

        int cnt = counts[b];
        float pv[P_POS];
        float m4 = -INFINITY;
#pragma unroll
        for (int j = 0; j < P_POS; ++j) {
            pv[j] = g_pos[b * P_POS + j];
            m4 = fmaxf(m4, pv[j]);
        }
        float se = 0.f, wp = 0.f, al = 0.f;
#pragma unroll
        for (int j = 0; j < P_POS; ++j) {
            if (j < cnt) al += logaddexpf_(pv[j], lse) - pv[j];
            float e = expf(pv[j] - m4);
            se += e;
            wp += e * pv[j];
        }
        if (cnt > 1) {
            float wps = wp / se;
            al += ALPHA_W * (logaddexpf_(wps, lse) - wps);
        }
        local += al;
    }

    red[tid] = local;
    __syncthreads();
    for (int o = 128; o > 0; o >>= 1) {
        if (tid < o) red[tid] += red[tid + o];
        __syncthreads();
    }
    if (tid == 0) out[0] = red[0] / (float)B_ANCH;
}

// ---------------------------------------------------------------------------
extern "C" void kernel_launch(void* const* d_in, const int* in_sizes, int n_in,
                              void* d_out, int out_size) {
    const float* anc = (const float*)d_in[0];
    const float* pos = (const float*)d_in[1];
    const float* neg = (const float*)d_in[2];
    const int*   cnt = (const int*)d_in[3];
    float* out = (float*)d_out;
    (void)in_sizes; (void)n_in; (void)out_size;

    cudaFuncSetAttribute(neg_mma_kernel,
                         cudaFuncAttributeMaxDynamicSharedMemorySize, SMEM_TOTAL);

    norm_rows_kernel<<<B_ANCH / 8, 256>>>(anc, B_ANCH, 0);
    norm_rows_kernel<<<NNEG / 8, 256>>>(neg, NNEG, 1);
    pos_sim_kernel<<<(B_ANCH * P_POS) / 8, 256>>>(pos);
    neg_mma_kernel<<<dim3(B_ANCH / MT, NSPLIT), 256, SMEM_TOTAL>>>();
    finalize_kernel<<<1, 256>>>(cnt, out);
}